// round 1
// baseline (speedup 1.0000x reference)
#include <cuda_runtime.h>
#include <cuda_bf16.h>

#define Bb 256
#define Tt 1024
#define INF 128
#define Hh 10
#define OUTD 128
#define BT (Bb*Tt)

// Scratch (no cudaMalloc allowed): device globals
__device__ float g_xp0[(size_t)BT * Hh];   // [BT][10]
__device__ float g_out2[(size_t)BT * Hh];  // [BT][10]

// ---------------------------------------------------------------------------
// Kernel 1: xp0[row][h] = dot(x[row,:], W_ih0[h,:]) + b_ih0[h] + b_hh0[h]
// 4 rows per thread; x read as float4 (coalesced, L1 line reuse 8x);
// W_ih0 staged transposed in smem as float4 Wq[f][3] (broadcast LDS).
// ---------------------------------------------------------------------------
__global__ __launch_bounds__(256) void k1_inproj(
    const float* __restrict__ x,
    const float* __restrict__ W_ih0,
    const float* __restrict__ b_ih0,
    const float* __restrict__ b_hh0)
{
    __shared__ float4 Wq[128][3];   // Wq[f][g] holds W_ih0[4g..4g+3][f] (h>=10 -> 0)
    __shared__ float bs[16];
    int tid = threadIdx.x;
    for (int i = tid; i < 128 * 3; i += blockDim.x) {
        int f = i / 3, g = i % 3;
        float4 v;
        v.x = (4*g+0 < Hh) ? W_ih0[(4*g+0)*128 + f] : 0.f;
        v.y = (4*g+1 < Hh) ? W_ih0[(4*g+1)*128 + f] : 0.f;
        v.z = (4*g+2 < Hh) ? W_ih0[(4*g+2)*128 + f] : 0.f;
        v.w = (4*g+3 < Hh) ? W_ih0[(4*g+3)*128 + f] : 0.f;
        Wq[f][g] = v;
    }
    if (tid < Hh) bs[tid] = b_ih0[tid] + b_hh0[tid];
    __syncthreads();

    const int ROWS = 4;
    size_t row0 = (size_t)blockIdx.x * (blockDim.x * ROWS) + tid;
    const float4* x4 = (const float4*)x;

    float acc[ROWS][Hh];
    #pragma unroll
    for (int r = 0; r < ROWS; r++)
        #pragma unroll
        for (int h = 0; h < Hh; h++) acc[r][h] = bs[h];

    #pragma unroll 4
    for (int c = 0; c < 32; c++) {
        float4 xv[ROWS];
        #pragma unroll
        for (int r = 0; r < ROWS; r++)
            xv[r] = x4[(row0 + (size_t)r * 256) * 32 + c];
        #pragma unroll
        for (int q = 0; q < 4; q++) {
            int f = 4 * c + q;
            float4 wa = Wq[f][0], wb = Wq[f][1], wc = Wq[f][2];
            #pragma unroll
            for (int r = 0; r < ROWS; r++) {
                float xs = (q == 0) ? xv[r].x : (q == 1) ? xv[r].y
                         : (q == 2) ? xv[r].z : xv[r].w;
                acc[r][0] = fmaf(xs, wa.x, acc[r][0]);
                acc[r][1] = fmaf(xs, wa.y, acc[r][1]);
                acc[r][2] = fmaf(xs, wa.z, acc[r][2]);
                acc[r][3] = fmaf(xs, wa.w, acc[r][3]);
                acc[r][4] = fmaf(xs, wb.x, acc[r][4]);
                acc[r][5] = fmaf(xs, wb.y, acc[r][5]);
                acc[r][6] = fmaf(xs, wb.z, acc[r][6]);
                acc[r][7] = fmaf(xs, wb.w, acc[r][7]);
                acc[r][8] = fmaf(xs, wc.x, acc[r][8]);
                acc[r][9] = fmaf(xs, wc.y, acc[r][9]);
            }
        }
    }
    #pragma unroll
    for (int r = 0; r < ROWS; r++) {
        float* o = g_xp0 + (row0 + (size_t)r * 256) * Hh;
        #pragma unroll
        for (int h = 0; h < Hh; h++) o[h] = acc[r][h];
    }
}

// ---------------------------------------------------------------------------
// Kernel 2: fused 2-layer ReLU RNN scan. One warp per batch.
// Lane j (j<10) owns h0[j], h1[j]; weight rows in registers; cross-lane
// broadcasts via shfl. xp0 prefetched in register chunks of 8.
// ---------------------------------------------------------------------------
__global__ __launch_bounds__(64) void k2_scan(
    const float* __restrict__ W_hh0,
    const float* __restrict__ W_ih1,
    const float* __restrict__ W_hh1,
    const float* __restrict__ b_ih1,
    const float* __restrict__ b_hh1,
    float* __restrict__ dout)
{
    const unsigned FULL = 0xffffffffu;
    int warp = (blockIdx.x * blockDim.x + threadIdx.x) >> 5;   // = batch b
    int lane = threadIdx.x & 31;
    int j = lane < Hh ? lane : Hh - 1;

    float w0[Hh], wi1[Hh], w1[Hh];
    #pragma unroll
    for (int k = 0; k < Hh; k++) {
        w0[k]  = W_hh0[j * Hh + k];
        wi1[k] = W_ih1[j * Hh + k];
        w1[k]  = W_hh1[j * Hh + k];
    }
    float bias1 = b_ih1[j] + b_hh1[j];

    const float* xp = g_xp0 + (size_t)warp * Tt * Hh;
    float* o2 = g_out2 + (size_t)warp * Tt * Hh;

    float h0 = 0.f, h1 = 0.f;
    float xa[8], xb[8];
    #pragma unroll
    for (int d = 0; d < 8; d++) xa[d] = xp[d * Hh + j];

    for (int tb = 0; tb < Tt; tb += 8) {
        if (tb + 8 < Tt) {
            #pragma unroll
            for (int d = 0; d < 8; d++) xb[d] = xp[(tb + 8 + d) * Hh + j];
        }
        #pragma unroll
        for (int d = 0; d < 8; d++) {
            // layer0 recurrence + layer1 recurrent part (independent -> overlap)
            float a0 = xa[d], a1 = 0.f;        // xp0 already includes both biases
            float r0 = bias1, r1 = 0.f;
            #pragma unroll
            for (int k = 0; k < Hh; k += 2) {
                float hk0 = __shfl_sync(FULL, h0, k);
                float hk1 = __shfl_sync(FULL, h0, k + 1);
                float gk0 = __shfl_sync(FULL, h1, k);
                float gk1 = __shfl_sync(FULL, h1, k + 1);
                a0 = fmaf(w0[k],     hk0, a0);
                a1 = fmaf(w0[k + 1], hk1, a1);
                r0 = fmaf(w1[k],     gk0, r0);
                r1 = fmaf(w1[k + 1], gk1, r1);
            }
            float h0n = fmaxf(a0 + a1, 0.f);
            float c0 = r0, c1 = r1;
            #pragma unroll
            for (int k = 0; k < Hh; k += 2) {
                float nk0 = __shfl_sync(FULL, h0n, k);
                float nk1 = __shfl_sync(FULL, h0n, k + 1);
                c0 = fmaf(wi1[k],     nk0, c0);
                c1 = fmaf(wi1[k + 1], nk1, c1);
            }
            float h1n = fmaxf(c0 + c1, 0.f);
            if (lane < Hh) o2[(tb + d) * Hh + lane] = h1n;
            h0 = h0n; h1 = h1n;
        }
        #pragma unroll
        for (int d = 0; d < 8; d++) xa[d] = xb[d];
    }

    if (lane < Hh) {
        float* hid = dout + (size_t)BT * OUTD;   // hidden: [2][B][H]
        hid[warp * Hh + lane] = h0;              // layer 0 final state
        hid[Bb * Hh + warp * Hh + lane] = h1;    // layer 1 final state
    }
}

// ---------------------------------------------------------------------------
// Kernel 3: logits = out2 @ W_lin^T + b_lin, softmax over 128.
// One warp per row; lane handles outputs 4l..4l+3; coalesced STG.128.
// ---------------------------------------------------------------------------
__global__ __launch_bounds__(256) void k3_head(
    const float* __restrict__ W_lin,
    const float* __restrict__ b_lin,
    float* __restrict__ out)
{
    const unsigned FULL = 0xffffffffu;
    __shared__ float Wl[OUTD * Hh];
    __shared__ float bl[OUTD];
    int tid = threadIdx.x;
    for (int i = tid; i < OUTD * Hh; i += blockDim.x) Wl[i] = W_lin[i];
    for (int i = tid; i < OUTD; i += blockDim.x) bl[i] = b_lin[i];
    __syncthreads();

    int lane = tid & 31;
    int wib  = tid >> 5;
    float wl[4][Hh], bb[4];
    #pragma unroll
    for (int c = 0; c < 4; c++) {
        int o = 4 * lane + c;
        bb[c] = bl[o];
        #pragma unroll
        for (int k = 0; k < Hh; k++) wl[c][k] = Wl[o * Hh + k];
    }

    int wpb = blockDim.x >> 5;
    int gw  = blockIdx.x * wpb + wib;
    int nw  = gridDim.x * wpb;
    for (int row = gw; row < BT; row += nw) {
        float v = g_out2[(size_t)row * Hh + (lane < Hh ? lane : 0)];
        float hk[Hh];
        #pragma unroll
        for (int k = 0; k < Hh; k++) hk[k] = __shfl_sync(FULL, v, k);

        float acc[4];
        #pragma unroll
        for (int c = 0; c < 4; c++) {
            acc[c] = bb[c];
            #pragma unroll
            for (int k = 0; k < Hh; k++) acc[c] = fmaf(hk[k], wl[c][k], acc[c]);
        }
        float m = fmaxf(fmaxf(acc[0], acc[1]), fmaxf(acc[2], acc[3]));
        #pragma unroll
        for (int s = 16; s > 0; s >>= 1)
            m = fmaxf(m, __shfl_xor_sync(FULL, m, s));
        float e0 = __expf(acc[0] - m), e1 = __expf(acc[1] - m);
        float e2 = __expf(acc[2] - m), e3 = __expf(acc[3] - m);
        float s = e0 + e1 + e2 + e3;
        #pragma unroll
        for (int sh = 16; sh > 0; sh >>= 1)
            s += __shfl_xor_sync(FULL, s, sh);
        float r = __frcp_rn(s);
        float4 res = make_float4(e0 * r, e1 * r, e2 * r, e3 * r);
        ((float4*)(out + (size_t)row * OUTD))[lane] = res;
    }
}

// ---------------------------------------------------------------------------
extern "C" void kernel_launch(void* const* d_in, const int* in_sizes, int n_in,
                              void* d_out, int out_size)
{
    const float* x      = (const float*)d_in[0];
    const float* W_ih0  = (const float*)d_in[1];
    const float* W_hh0  = (const float*)d_in[2];
    const float* b_ih0  = (const float*)d_in[3];
    const float* b_hh0  = (const float*)d_in[4];
    const float* W_ih1  = (const float*)d_in[5];
    const float* W_hh1  = (const float*)d_in[6];
    const float* b_ih1  = (const float*)d_in[7];
    const float* b_hh1  = (const float*)d_in[8];
    const float* W_lin  = (const float*)d_in[9];
    const float* b_lin  = (const float*)d_in[10];
    float* out = (float*)d_out;

    k1_inproj<<<256, 256>>>(x, W_ih0, b_ih0, b_hh0);           // BT rows, 4/thread
    k2_scan<<<128, 64>>>(W_hh0, W_ih1, W_hh1, b_ih1, b_hh1, out); // 256 warps = B
    k3_head<<<2048, 256>>>(W_lin, b_lin, out);                 // grid-stride rows
}